// round 8
// baseline (speedup 1.0000x reference)
#include <cuda_runtime.h>

#define VTH 0.5f
#define TAU 0.2f

__device__ __forceinline__ float4 lif4(float4 v) {
    float u = v.x;
    float s0 = (u > VTH) ? 1.0f : 0.0f;
    u = TAU * u * (1.0f - s0) + v.y;
    float s1 = (u > VTH) ? 1.0f : 0.0f;
    u = TAU * u * (1.0f - s1) + v.z;
    float s2 = (u > VTH) ? 1.0f : 0.0f;
    u = TAU * u * (1.0f - s2) + v.w;
    float s3 = (u > VTH) ? 1.0f : 0.0f;
    return make_float4(s0, s1, s2, s3);
}

// x: [N, 4] f32, steps innermost. Each thread: 8 float4 neurons, all loads
// front-batched (MLP_p1=8), streaming cache policy on loads and stores.
__global__ void __launch_bounds__(256) lif_kernel8(const float4* __restrict__ x,
                                                   float4* __restrict__ out,
                                                   int n4) {
    int base = blockIdx.x * (blockDim.x * 8) + threadIdx.x;

    int idx[8];
#pragma unroll
    for (int j = 0; j < 8; j++) idx[j] = base + j * blockDim.x;

    if (idx[7] < n4) {
        // Fast path (uniform within block): 8 independent loads back-to-back.
        float4 v[8];
#pragma unroll
        for (int j = 0; j < 8; j++) v[j] = __ldcs(&x[idx[j]]);
        float4 r[8];
#pragma unroll
        for (int j = 0; j < 8; j++) r[j] = lif4(v[j]);
#pragma unroll
        for (int j = 0; j < 8; j++) __stcs(&out[idx[j]], r[j]);
    } else {
#pragma unroll
        for (int j = 0; j < 8; j++)
            if (idx[j] < n4) __stcs(&out[idx[j]], lif4(__ldcs(&x[idx[j]])));
    }
}

extern "C" void kernel_launch(void* const* d_in, const int* in_sizes, int n_in,
                              void* d_out, int out_size) {
    const float4* x = (const float4*)d_in[0];
    float4* out = (float4*)d_out;
    int n4 = out_size / 4;  // neurons (4 contiguous f32 steps each)

    int threads = 256;
    int per_block = threads * 8;
    int blocks = (n4 + per_block - 1) / per_block;
    lif_kernel8<<<blocks, threads>>>(x, out, n4);
}